// round 9
// baseline (speedup 1.0000x reference)
#include <cuda_runtime.h>
#include <cuda_bf16.h>
#include <cstdint>

// TELIF: temporal-encoded LIF spiking neuron scan.
// tx: [T, B, N] f32, TE: [N, T] f32 -> ty: [T, B, N] f32.
//
// R9: single-kernel warp-specialized pipeline (R8 core, which took DRAM
// 43%->66.5%, kept intact). Changes:
//  - TE transpose kernel ELIMINATED: producer lanes read TE in native [N,T]
//    layout (each lane's chunk = 32 contiguous bytes = 2x cp.async.cg 16)
//    into smem [lane][8]; consumers read it back as 2x LDS.128.
//  - Consumer LDS count per chunk: 16 -> 10.
// One launch, 1024 blocks x 128 threads (2 producer + 2 consumer warps).

#define T_STEPS 512
#define B_DIM   64
#define N_DIM   1024
#define BN      (B_DIM * N_DIM)

#define REST      0.0f
#define DECAY     0.2f
#define THRESHOLD 0.3f
#define BETA      0.02f

#define CHUNK    8                    // time steps per stage
#define NCHUNK   (T_STEPS / CHUNK)    // 64
#define STAGES   6
#define LAG      4                    // commit-group completion lag
#define PAIRS    2                    // warp pairs per block
#define BLKT     (PAIRS * 64)         // 128 threads: warps 0,1 prod; 2,3 cons

// ---------------------------------------------------------------------------
// PTX helpers
// ---------------------------------------------------------------------------
__device__ __forceinline__ uint32_t smem_u32(const void* p) {
    return (uint32_t)__cvta_generic_to_shared(p);
}
__device__ __forceinline__ void cp_async16(uint32_t saddr, const void* gptr) {
    asm volatile("cp.async.cg.shared.global [%0], [%1], 16;\n"
                 :: "r"(saddr), "l"(gptr));
}
__device__ __forceinline__ void cp_commit() {
    asm volatile("cp.async.commit_group;\n");
}
__device__ __forceinline__ void cp_wait_lag() {
    asm volatile("cp.async.wait_group 4;\n" ::: "memory");
}
__device__ __forceinline__ void cp_wait_all() {
    asm volatile("cp.async.wait_group 0;\n" ::: "memory");
}
__device__ __forceinline__ void mbar_init(uint32_t a, uint32_t cnt) {
    asm volatile("mbarrier.init.shared.b64 [%0], %1;\n" :: "r"(a), "r"(cnt) : "memory");
}
__device__ __forceinline__ void mbar_arrive(uint32_t a) {
    asm volatile("mbarrier.arrive.release.cta.shared::cta.b64 _, [%0];\n"
                 :: "r"(a) : "memory");
}
__device__ __forceinline__ void mbar_wait(uint32_t a, uint32_t phase) {
    uint32_t done;
    asm volatile(
        "{\n\t.reg .pred p;\n\t"
        "mbarrier.try_wait.parity.acquire.cta.shared::cta.b64 p, [%1], %2;\n\t"
        "selp.b32 %0, 1, 0, p;\n\t}"
        : "=r"(done) : "r"(a), "r"(phase) : "memory");
    if (!done) {
        asm volatile(
            "{\n\t.reg .pred P1;\n\t"
            "WL_%=:\n\t"
            "mbarrier.try_wait.parity.acquire.cta.shared::cta.b64 P1, [%0], %1;\n\t"
            "@P1 bra.uni WD_%=;\n\t"
            "bra.uni WL_%=;\n\t"
            "WD_%=:\n\t}"
            :: "r"(a), "r"(phase) : "memory");
    }
}

// ---------------------------------------------------------------------------
// Main scan: producer/consumer warp pairs over 32 neurons each.
// smem: tx tile [pair][stage][step][lane]; te tile [pair][stage][lane][step]
// ---------------------------------------------------------------------------
__global__ void __launch_bounds__(BLKT)
telif_scan(const float* __restrict__ tx, const float* __restrict__ TE,
           float* __restrict__ out) {
    __shared__ __align__(16) float stx[PAIRS][STAGES][CHUNK][32];
    __shared__ __align__(16) float ste[PAIRS][STAGES][32][CHUNK];
    __shared__ __align__(8)  uint64_t mb_full[PAIRS][STAGES];
    __shared__ __align__(8)  uint64_t mb_empty[PAIRS][STAGES];

    const int tid  = threadIdx.x;
    const int wid  = tid >> 5;
    const int lane = tid & 31;
    const bool producer = (wid < PAIRS);
    const int p = producer ? wid : (wid - PAIRS);

    const int pairbase = blockIdx.x * (PAIRS * 32) + p * 32;

    if (tid == 0) {
#pragma unroll
        for (int q = 0; q < PAIRS; q++)
#pragma unroll
            for (int s = 0; s < STAGES; s++) {
                mbar_init(smem_u32(&mb_full[q][s]), 32);
                mbar_init(smem_u32(&mb_empty[q][s]), 32);
            }
    }
    __syncthreads();

    if (producer) {
        // ------------------ producer warp: pure memory pump ------------------
        const float* txb = tx + pairbase;
        // This lane's TE row (native [N, T] layout): neuron n0 + lane.
        const float* terow = TE + (size_t)((pairbase & (N_DIM - 1)) + lane) * T_STEPS;

        // tx split: k = lane + 32j -> step st = k>>3, 16B seg = (k&7)*4 floats.
        const int k0  = lane;
        const int k1  = lane + 32;
        const int st0 = k0 >> 3, sg0 = (k0 & 7) * 4;
        const int st1 = k1 >> 3, sg1 = (k1 & 7) * 4;

        int es = 0, eph = 1;     // empty-wait cursor
        int as = 0;              // full-arrive cursor (lags by LAG)

#pragma unroll 1
        for (int c = 0; c < NCHUNK; c++) {
            mbar_wait(smem_u32(&mb_empty[p][es]), eph);

            const float* ctx = txb + (size_t)(c * CHUNK) * BN;
            const float* cte = terow + c * CHUNK;   // 32B contiguous
            cp_async16(smem_u32(&stx[p][es][st0][sg0]), ctx + (size_t)st0 * BN + sg0);
            cp_async16(smem_u32(&stx[p][es][st1][sg1]), ctx + (size_t)st1 * BN + sg1);
            cp_async16(smem_u32(&ste[p][es][lane][0]), cte);
            cp_async16(smem_u32(&ste[p][es][lane][4]), cte + 4);
            cp_commit();

            if (c >= LAG) {
                cp_wait_lag();                       // group c-LAG complete
                mbar_arrive(smem_u32(&mb_full[p][as]));
                if (++as == STAGES) as = 0;
            }
            if (++es == STAGES) { es = 0; eph ^= 1; }
        }
        // Tail: flush last LAG chunks.
        cp_wait_all();
#pragma unroll
        for (int r = 0; r < LAG; r++) {
            mbar_arrive(smem_u32(&mb_full[p][as]));
            if (++as == STAGES) as = 0;
        }
    } else {
        // ------------------ consumer warp: LDS -> LIF -> STG -----------------
        const int idx = pairbase + lane;
        float* op = out + idx;

        float v  = REST;
        float y  = 0.0f;
        float th = THRESHOLD;

        int fs = 0, fph = 0;     // full-wait cursor

#pragma unroll 1
        for (int c = 0; c < NCHUNK; c++) {
            mbar_wait(smem_u32(&mb_full[p][fs]), fph);

            // te: this lane's 8 steps are contiguous -> 2x LDS.128.
            float4 ta = *reinterpret_cast<const float4*>(&ste[p][fs][lane][0]);
            float4 tb = *reinterpret_cast<const float4*>(&ste[p][fs][lane][4]);
            float tr[CHUNK] = {ta.x, ta.y, ta.z, ta.w, tb.x, tb.y, tb.z, tb.w};

            float xr[CHUNK];
#pragma unroll
            for (int s = 0; s < CHUNK; s++)
                xr[s] = stx[p][fs][s][lane];

#pragma unroll
            for (int s = 0; s < CHUNK; s++) {
                th = th + v * tr[s] - (th - THRESHOLD) * BETA;
                v  = v * DECAY * (1.0f - y) + xr[s];
                y  = (v > th) ? 1.0f : 0.0f;
                op[(size_t)(c * CHUNK + s) * BN] = y;
            }

            mbar_arrive(smem_u32(&mb_empty[p][fs]));
            if (++fs == STAGES) { fs = 0; fph ^= 1; }
        }
    }
}

// ---------------------------------------------------------------------------
// Launch
// ---------------------------------------------------------------------------
extern "C" void kernel_launch(void* const* d_in, const int* in_sizes, int n_in,
                              void* d_out, int out_size) {
    const float* tx = (const float*)d_in[0];   // [T, B, N]
    const float* TE = (const float*)d_in[1];   // [N, T]
    float* out = (float*)d_out;                // [T, B, N]

    (void)in_sizes; (void)n_in; (void)out_size;

    telif_scan<<<BN / (PAIRS * 32), BLKT>>>(tx, TE, out);
}

// round 10
// speedup vs baseline: 1.2746x; 1.2746x over previous
#include <cuda_runtime.h>
#include <cuda_bf16.h>
#include <cstdint>

// TELIF: temporal-encoded LIF spiking neuron scan.
// tx: [T, B, N] f32, TE: [N, T] f32 -> ty: [T, B, N] f32.
//
// R10 = R8 core (warp-specialized producer/consumer, transposed TE, DRAM
// 66.5%) with the TE transpose folded into the scan kernel behind a software
// global barrier (all 1024 blocks provably co-resident: smem-limited
// residency = 9 blocks/SM * 148 = 1332 >= 1024). Saves the ~6.5us serialized
// second launch. R9's native-layout TE cp.async (32 L1tex wavefronts per
// instruction) is reverted.

#define T_STEPS 512
#define B_DIM   64
#define N_DIM   1024
#define BN      (B_DIM * N_DIM)

#define REST      0.0f
#define DECAY     0.2f
#define THRESHOLD 0.3f
#define BETA      0.02f

#define CHUNK    8                    // time steps per stage
#define NCHUNK   (T_STEPS / CHUNK)    // 64
#define STAGES   6
#define LAG      4                    // commit-group completion lag
#define PAIRS    2                    // warp pairs per block
#define BLKT     (PAIRS * 64)         // 128 threads: warps 0,1 prod; 2,3 cons
#define GRID     (BN / (PAIRS * 32))  // 1024 blocks

__device__ float g_te_t[T_STEPS * N_DIM];        // TE transposed to [T][N]
__device__ unsigned int g_bar;                   // global barrier (monotonic)

// ---------------------------------------------------------------------------
// PTX helpers
// ---------------------------------------------------------------------------
__device__ __forceinline__ uint32_t smem_u32(const void* p) {
    return (uint32_t)__cvta_generic_to_shared(p);
}
__device__ __forceinline__ void cp_async16(uint32_t saddr, const void* gptr) {
    asm volatile("cp.async.cg.shared.global [%0], [%1], 16;\n"
                 :: "r"(saddr), "l"(gptr));
}
__device__ __forceinline__ void cp_commit() {
    asm volatile("cp.async.commit_group;\n");
}
__device__ __forceinline__ void cp_wait_lag() {
    asm volatile("cp.async.wait_group 4;\n" ::: "memory");
}
__device__ __forceinline__ void cp_wait_all() {
    asm volatile("cp.async.wait_group 0;\n" ::: "memory");
}
__device__ __forceinline__ void mbar_init(uint32_t a, uint32_t cnt) {
    asm volatile("mbarrier.init.shared.b64 [%0], %1;\n" :: "r"(a), "r"(cnt) : "memory");
}
__device__ __forceinline__ void mbar_arrive(uint32_t a) {
    asm volatile("mbarrier.arrive.release.cta.shared::cta.b64 _, [%0];\n"
                 :: "r"(a) : "memory");
}
__device__ __forceinline__ void mbar_wait(uint32_t a, uint32_t phase) {
    uint32_t done;
    asm volatile(
        "{\n\t.reg .pred p;\n\t"
        "mbarrier.try_wait.parity.acquire.cta.shared::cta.b64 p, [%1], %2;\n\t"
        "selp.b32 %0, 1, 0, p;\n\t}"
        : "=r"(done) : "r"(a), "r"(phase) : "memory");
    if (!done) {
        asm volatile(
            "{\n\t.reg .pred P1;\n\t"
            "WL_%=:\n\t"
            "mbarrier.try_wait.parity.acquire.cta.shared::cta.b64 P1, [%0], %1;\n\t"
            "@P1 bra.uni WD_%=;\n\t"
            "bra.uni WL_%=;\n\t"
            "WD_%=:\n\t}"
            :: "r"(a), "r"(phase) : "memory");
    }
}

// ---------------------------------------------------------------------------
// Main kernel: TE transpose phase -> global barrier -> R8 pipeline.
// smem stage layout: [pair][stage][arr(tx=0,te=1)][step][lane]
// ---------------------------------------------------------------------------
__global__ void __launch_bounds__(BLKT)
telif_scan(const float* __restrict__ tx, const float* __restrict__ TE,
           float* __restrict__ out) {
    __shared__ __align__(16) float stg[PAIRS][STAGES][2][CHUNK][32];
    __shared__ __align__(8)  uint64_t mb_full[PAIRS][STAGES];
    __shared__ __align__(8)  uint64_t mb_empty[PAIRS][STAGES];

    const int tid  = threadIdx.x;
    const int wid  = tid >> 5;
    const int lane = tid & 31;

    // ---------------- Phase 0: cooperative TE transpose -------------------
    // 1024 blocks = 32 n-tiles x 32 t-tiles; tile = 32 n x 16 t.
    {
        // Reuse pipeline smem as transpose scratch: 32 x 17 floats (padded).
        float (*tile)[17] = reinterpret_cast<float (*)[17]>(&stg[0][0][0][0][0]);
        const int nb = blockIdx.x & 31;          // n-tile
        const int tb = blockIdx.x >> 5;          // t-tile
        const int n0 = nb * 32;
        const int t0 = tb * 16;

        // Read TE[n0+r][t0+j], 8 rows x 16 t per rep (coalesced along t).
        {
            const int r = tid >> 4;              // 0..7
            const int j = tid & 15;
#pragma unroll
            for (int rep = 0; rep < 4; rep++) {
                int rr = r + rep * 8;
                tile[rr][j] = TE[(size_t)(n0 + rr) * T_STEPS + (t0 + j)];
            }
        }
        __syncthreads();
        // Write g_te_t[t0+jj][n0+rr] (coalesced along n).
        {
            const int rr = tid & 31;
            const int j0 = tid >> 5;             // 0..3
#pragma unroll
            for (int rep = 0; rep < 4; rep++) {
                int jj = j0 + rep * 4;
                g_te_t[(size_t)(t0 + jj) * N_DIM + (n0 + rr)] = tile[rr][jj];
            }
        }
        __threadfence();
        __syncthreads();

        // Global barrier (all 1024 blocks are co-resident; replay-safe:
        // each launch adds exactly GRID arrivals, counter is monotonic).
        if (tid == 0) {
            unsigned int old = atomicAdd(&g_bar, 1u);
            unsigned int target = old - (old & (GRID - 1)) + GRID;
            while (true) {
                unsigned int cur;
                asm volatile("ld.acquire.gpu.u32 %0, [%1];"
                             : "=r"(cur) : "l"(&g_bar));
                if (cur >= target) break;
                __nanosleep(128);
            }
        }
        __syncthreads();   // releases whole block; acquire above orders g_te_t
    }

    // ---------------- Phase 1: R8 producer/consumer pipeline ---------------
    const bool producer = (wid < PAIRS);
    const int p = producer ? wid : (wid - PAIRS);
    const int pairbase = blockIdx.x * (PAIRS * 32) + p * 32;

    if (tid == 0) {
#pragma unroll
        for (int q = 0; q < PAIRS; q++)
#pragma unroll
            for (int s = 0; s < STAGES; s++) {
                mbar_init(smem_u32(&mb_full[q][s]), 32);
                mbar_init(smem_u32(&mb_empty[q][s]), 32);
            }
    }
    __syncthreads();

    if (producer) {
        // ------------------ producer warp: pure memory pump ------------------
        const float* txb = tx + pairbase;
        const float* teb = g_te_t + (pairbase & (N_DIM - 1));

        // cp.async split: k = lane + 32j -> step st = k>>3, seg = (k&7)*4.
        const int k0  = lane;
        const int k1  = lane + 32;
        const int st0 = k0 >> 3, sg0 = (k0 & 7) * 4;
        const int st1 = k1 >> 3, sg1 = (k1 & 7) * 4;

        int es = 0, eph = 1;     // empty-wait cursor
        int as = 0;              // full-arrive cursor (lags by LAG)

#pragma unroll 1
        for (int c = 0; c < NCHUNK; c++) {
            mbar_wait(smem_u32(&mb_empty[p][es]), eph);

            const float* ctx = txb + (size_t)(c * CHUNK) * BN;
            const float* cte = teb + (size_t)(c * CHUNK) * N_DIM;
            cp_async16(smem_u32(&stg[p][es][0][st0][sg0]), ctx + (size_t)st0 * BN + sg0);
            cp_async16(smem_u32(&stg[p][es][1][st0][sg0]), cte + (size_t)st0 * N_DIM + sg0);
            cp_async16(smem_u32(&stg[p][es][0][st1][sg1]), ctx + (size_t)st1 * BN + sg1);
            cp_async16(smem_u32(&stg[p][es][1][st1][sg1]), cte + (size_t)st1 * N_DIM + sg1);
            cp_commit();

            if (c >= LAG) {
                cp_wait_lag();                       // group c-LAG complete
                mbar_arrive(smem_u32(&mb_full[p][as]));
                if (++as == STAGES) as = 0;
            }
            if (++es == STAGES) { es = 0; eph ^= 1; }
        }
        // Tail: flush last LAG chunks.
        cp_wait_all();
#pragma unroll
        for (int r = 0; r < LAG; r++) {
            mbar_arrive(smem_u32(&mb_full[p][as]));
            if (++as == STAGES) as = 0;
        }
    } else {
        // ------------------ consumer warp: LDS -> LIF -> STG -----------------
        const int idx = pairbase + lane;
        float* op = out + idx;

        float v  = REST;
        float y  = 0.0f;
        float th = THRESHOLD;

        int fs = 0, fph = 0;     // full-wait cursor

#pragma unroll 1
        for (int c = 0; c < NCHUNK; c++) {
            mbar_wait(smem_u32(&mb_full[p][fs]), fph);

            float xr[CHUNK], tr[CHUNK];
#pragma unroll
            for (int s = 0; s < CHUNK; s++) {
                xr[s] = stg[p][fs][0][s][lane];
                tr[s] = stg[p][fs][1][s][lane];
            }

#pragma unroll
            for (int s = 0; s < CHUNK; s++) {
                th = th + v * tr[s] - (th - THRESHOLD) * BETA;
                v  = v * DECAY * (1.0f - y) + xr[s];
                y  = (v > th) ? 1.0f : 0.0f;
                op[(size_t)(c * CHUNK + s) * BN] = y;
            }

            mbar_arrive(smem_u32(&mb_empty[p][fs]));
            if (++fs == STAGES) { fs = 0; fph ^= 1; }
        }
    }
}

// ---------------------------------------------------------------------------
// Launch
// ---------------------------------------------------------------------------
extern "C" void kernel_launch(void* const* d_in, const int* in_sizes, int n_in,
                              void* d_out, int out_size) {
    const float* tx = (const float*)d_in[0];   // [T, B, N]
    const float* TE = (const float*)d_in[1];   // [N, T]
    float* out = (float*)d_out;                // [T, B, N]

    (void)in_sizes; (void)n_in; (void)out_size;

    telif_scan<<<GRID, BLKT>>>(tx, TE, out);
}

// round 11
// speedup vs baseline: 1.3525x; 1.0612x over previous
#include <cuda_runtime.h>
#include <cuda_bf16.h>
#include <cstdint>

// TELIF: temporal-encoded LIF spiking neuron scan.
// tx: [T, B, N] f32, TE: [N, T] f32 -> ty: [T, B, N] f32.
//
// R11 = R8 (two kernels, warp-specialized, transposed TE; best total 55.4us,
// scan 41.8us @ 66.5% DRAM) + float2 consumers. The LSU/L1tex port is still
// ~saturated in R8 (per-SM issue budget ~= kernel cycles), so the lever is
// fewer, wider consumer ops: per 64 neurons use 2 producer warps (unchanged)
// + 1 consumer warp with 2 neurons/lane (LDS.64 / STG.64, ILP-2 LIF chains).
// Consumer LDS issue 32->16, STG 16->8 per chunk. 1024 blocks x 96 threads.

#define T_STEPS 512
#define B_DIM   64
#define N_DIM   1024
#define BN      (B_DIM * N_DIM)

#define REST      0.0f
#define DECAY     0.2f
#define THRESHOLD 0.3f
#define BETA      0.02f

#define CHUNK    8                    // time steps per stage
#define NCHUNK   (T_STEPS / CHUNK)    // 64
#define STAGES   6
#define LAG      4                    // commit-group completion lag
#define HALVES   2                    // producer warps (32 neurons each)
#define BLKT     96                   // warps 0,1 = producers; warp 2 = consumer
#define GRID     (BN / 64)            // 1024 blocks, 64 neurons each

__device__ float g_te_t[T_STEPS * N_DIM];   // TE transposed to [T][N]

// ---------------------------------------------------------------------------
// Transpose TE [N, T] -> g_te_t [T, N]. 32x32 tiles, padded smem.
// ---------------------------------------------------------------------------
__global__ void telif_transpose_te(const float* __restrict__ TE) {
    __shared__ float tile[32][33];
    int n0 = blockIdx.x * 32;
    int t0 = blockIdx.y * 32;
    int lx = threadIdx.x;
    int ly = threadIdx.y;

#pragma unroll
    for (int i = 0; i < 32; i += 8)
        tile[ly + i][lx] = TE[(size_t)(n0 + ly + i) * T_STEPS + (t0 + lx)];
    __syncthreads();
#pragma unroll
    for (int i = 0; i < 32; i += 8)
        g_te_t[(size_t)(t0 + ly + i) * N_DIM + (n0 + lx)] = tile[lx][ly + i];
}

// ---------------------------------------------------------------------------
// PTX helpers
// ---------------------------------------------------------------------------
__device__ __forceinline__ uint32_t smem_u32(const void* p) {
    return (uint32_t)__cvta_generic_to_shared(p);
}
__device__ __forceinline__ void cp_async16(uint32_t saddr, const void* gptr) {
    asm volatile("cp.async.cg.shared.global [%0], [%1], 16;\n"
                 :: "r"(saddr), "l"(gptr));
}
__device__ __forceinline__ void cp_commit() {
    asm volatile("cp.async.commit_group;\n");
}
__device__ __forceinline__ void cp_wait_lag() {
    asm volatile("cp.async.wait_group 4;\n" ::: "memory");
}
__device__ __forceinline__ void cp_wait_all() {
    asm volatile("cp.async.wait_group 0;\n" ::: "memory");
}
__device__ __forceinline__ void mbar_init(uint32_t a, uint32_t cnt) {
    asm volatile("mbarrier.init.shared.b64 [%0], %1;\n" :: "r"(a), "r"(cnt) : "memory");
}
__device__ __forceinline__ void mbar_arrive(uint32_t a) {
    asm volatile("mbarrier.arrive.release.cta.shared::cta.b64 _, [%0];\n"
                 :: "r"(a) : "memory");
}
__device__ __forceinline__ void mbar_wait(uint32_t a, uint32_t phase) {
    uint32_t done;
    asm volatile(
        "{\n\t.reg .pred p;\n\t"
        "mbarrier.try_wait.parity.acquire.cta.shared::cta.b64 p, [%1], %2;\n\t"
        "selp.b32 %0, 1, 0, p;\n\t}"
        : "=r"(done) : "r"(a), "r"(phase) : "memory");
    if (!done) {
        asm volatile(
            "{\n\t.reg .pred P1;\n\t"
            "WL_%=:\n\t"
            "mbarrier.try_wait.parity.acquire.cta.shared::cta.b64 P1, [%0], %1;\n\t"
            "@P1 bra.uni WD_%=;\n\t"
            "bra.uni WL_%=;\n\t"
            "WD_%=:\n\t}"
            :: "r"(a), "r"(phase) : "memory");
    }
}

// ---------------------------------------------------------------------------
// Main scan: per block 64 neurons = 2 producer warps + 1 float2 consumer warp.
// smem stage layout: [half][stage][arr(tx=0,te=1)][step][lane32]
// ---------------------------------------------------------------------------
__global__ void __launch_bounds__(BLKT)
telif_scan(const float* __restrict__ tx, float* __restrict__ out) {
    __shared__ __align__(16) float stg[HALVES][STAGES][2][CHUNK][32];
    __shared__ __align__(8)  uint64_t mb_full[HALVES][STAGES];
    __shared__ __align__(8)  uint64_t mb_empty[HALVES][STAGES];

    const int tid  = threadIdx.x;
    const int wid  = tid >> 5;
    const int lane = tid & 31;
    const int blockbase = blockIdx.x * 64;        // first (b*N+n) of block

    if (tid == 0) {
#pragma unroll
        for (int h = 0; h < HALVES; h++)
#pragma unroll
            for (int s = 0; s < STAGES; s++) {
                mbar_init(smem_u32(&mb_full[h][s]), 32);
                mbar_init(smem_u32(&mb_empty[h][s]), 32);
            }
    }
    __syncthreads();

    if (wid < HALVES) {
        // ------------------ producer warp (unchanged R8 pump) ----------------
        const int p = wid;
        const int pairbase = blockbase + p * 32;
        const float* txb = tx + pairbase;
        const float* teb = g_te_t + (pairbase & (N_DIM - 1));

        // cp.async split: k = lane + 32j -> step st = k>>3, seg = (k&7)*4.
        const int k0  = lane;
        const int k1  = lane + 32;
        const int st0 = k0 >> 3, sg0 = (k0 & 7) * 4;
        const int st1 = k1 >> 3, sg1 = (k1 & 7) * 4;

        int es = 0, eph = 1;     // empty-wait cursor
        int as = 0;              // full-arrive cursor (lags by LAG)

#pragma unroll 1
        for (int c = 0; c < NCHUNK; c++) {
            mbar_wait(smem_u32(&mb_empty[p][es]), eph);

            const float* ctx = txb + (size_t)(c * CHUNK) * BN;
            const float* cte = teb + (size_t)(c * CHUNK) * N_DIM;
            cp_async16(smem_u32(&stg[p][es][0][st0][sg0]), ctx + (size_t)st0 * BN + sg0);
            cp_async16(smem_u32(&stg[p][es][1][st0][sg0]), cte + (size_t)st0 * N_DIM + sg0);
            cp_async16(smem_u32(&stg[p][es][0][st1][sg1]), ctx + (size_t)st1 * BN + sg1);
            cp_async16(smem_u32(&stg[p][es][1][st1][sg1]), cte + (size_t)st1 * N_DIM + sg1);
            cp_commit();

            if (c >= LAG) {
                cp_wait_lag();                       // group c-LAG complete
                mbar_arrive(smem_u32(&mb_full[p][as]));
                if (++as == STAGES) as = 0;
            }
            if (++es == STAGES) { es = 0; eph ^= 1; }
        }
        // Tail: flush last LAG chunks.
        cp_wait_all();
#pragma unroll
        for (int r = 0; r < LAG; r++) {
            mbar_arrive(smem_u32(&mb_full[p][as]));
            if (++as == STAGES) as = 0;
        }
    } else {
        // -------------- consumer warp: 2 neurons per lane (float2) ----------
        // lane l -> global neurons blockbase + 2l, 2l+1.
        //   half h = l >> 4, in-buffer float2 index = (2l) & 31.
        const int h  = lane >> 4;
        const int j2 = (2 * lane) & 31;
        float* op = out + blockbase + 2 * lane;     // float2-aligned (8B)

        float2 v  = make_float2(REST, REST);
        float2 y  = make_float2(0.0f, 0.0f);
        float2 th = make_float2(THRESHOLD, THRESHOLD);

        int fs = 0, fph = 0;     // full-wait cursor

#pragma unroll 1
        for (int c = 0; c < NCHUNK; c++) {
            // Need both halves' data for this stage.
            mbar_wait(smem_u32(&mb_full[0][fs]), fph);
            mbar_wait(smem_u32(&mb_full[1][fs]), fph);

            float2 xr[CHUNK], tr[CHUNK];
#pragma unroll
            for (int s = 0; s < CHUNK; s++) {
                xr[s] = *reinterpret_cast<const float2*>(&stg[h][fs][0][s][j2]);
                tr[s] = *reinterpret_cast<const float2*>(&stg[h][fs][1][s][j2]);
            }

#pragma unroll
            for (int s = 0; s < CHUNK; s++) {
                th.x = th.x + v.x * tr[s].x - (th.x - THRESHOLD) * BETA;
                th.y = th.y + v.y * tr[s].y - (th.y - THRESHOLD) * BETA;
                v.x  = v.x * DECAY * (1.0f - y.x) + xr[s].x;
                v.y  = v.y * DECAY * (1.0f - y.y) + xr[s].y;
                y.x  = (v.x > th.x) ? 1.0f : 0.0f;
                y.y  = (v.y > th.y) ? 1.0f : 0.0f;
                *reinterpret_cast<float2*>(op + (size_t)(c * CHUNK + s) * BN) = y;
            }

            mbar_arrive(smem_u32(&mb_empty[0][fs]));
            mbar_arrive(smem_u32(&mb_empty[1][fs]));
            if (++fs == STAGES) { fs = 0; fph ^= 1; }
        }
    }
}

// ---------------------------------------------------------------------------
// Launch
// ---------------------------------------------------------------------------
extern "C" void kernel_launch(void* const* d_in, const int* in_sizes, int n_in,
                              void* d_out, int out_size) {
    const float* tx = (const float*)d_in[0];   // [T, B, N]
    const float* TE = (const float*)d_in[1];   // [N, T]
    float* out = (float*)d_out;                // [T, B, N]

    (void)in_sizes; (void)n_in; (void)out_size;

    dim3 tb(32, 8);
    dim3 tg(N_DIM / 32, T_STEPS / 32);
    telif_transpose_te<<<tg, tb>>>(TE);

    telif_scan<<<GRID, BLKT>>>(tx, out);
}